// round 10
// baseline (speedup 1.0000x reference)
#include <cuda_runtime.h>
#include <cuda_fp16.h>
#include <stdint.h>

// Static scratch (no device allocs allowed).
#define MAX_NODES 131072
#define BUCKET_CAP 64
#define MAX_SPILL 8192

__device__ int    g_cursor[MAX_NODES];               // per-node fill cursor == in-degree
__device__ int    g_bucket[MAX_NODES * BUCKET_CAP];  // src ids, 64 slots per node
__device__ __half g_feat16[MAX_NODES * 64];          // fp16 mirror of features (12.8 MB live)
__device__ int    g_spill_src[MAX_SPILL];
__device__ int    g_spill_dst[MAX_SPILL];
__device__ int    g_spill_n;
__device__ int    g_is64;                            // edge index dtype flag

// ---------------------------------------------------------------------------
// Kernel 1: convert features to fp16 mirror (half2 granularity), zero cursors
// and spill counter; block 0 additionally sniffs the edge-index dtype
// (int64 values < 2^31 have zero odd int32 words; int32 node ids are
// ~uniform in [0,1e5) and essentially never all zero over 2048 samples).
// ---------------------------------------------------------------------------
__global__ void convert_kernel(const float* __restrict__ feat,
                               const int* __restrict__ ei32, long long n_words,
                               int n_nodes) {
    int i = blockIdx.x * blockDim.x + threadIdx.x;

    int n_pairs = n_nodes * 32;      // half2 elements
    if (i < n_pairs) {
        float2 v = ((const float2*)feat)[i];
        ((__half2*)g_feat16)[i] = __float22half2_rn(v);
    }
    if (i < n_nodes) g_cursor[i] = 0;
    if (i == 0) g_spill_n = 0;

    if (blockIdx.x == 0) {
        __shared__ int nz;
        if (threadIdx.x == 0) nz = 0;
        __syncthreads();
        long long limit = n_words < 4096 ? n_words : 4096;
        for (long long j = threadIdx.x * 2 + 1; j < limit; j += blockDim.x * 2)
            if (ei32[j] != 0) atomicOr(&nz, 1);
        __syncthreads();
        if (threadIdx.x == 0) g_is64 = (nz == 0) ? 1 : 0;
    }
}

// ---------------------------------------------------------------------------
// Kernel 2: single edge pass — scatter src ids into fixed-capacity buckets.
// Two edges per thread with vectorized index loads for MLP.
// Overflow (vanishingly rare, P~1e-18/node) goes to the spill list.
// ---------------------------------------------------------------------------
__global__ void fill_kernel(const void* __restrict__ ei_raw, long long E) {
    long long t = (long long)blockIdx.x * blockDim.x + threadIdx.x;
    long long e0 = t * 2;
    if (e0 >= E) return;

    int s[2], d[2];
    int n = (e0 + 1 < E) ? 2 : 1;

    if (g_is64) {
        const long long* ei = (const long long*)ei_raw;
        if (n == 2) {
            longlong2 sv = *(const longlong2*)(ei + e0);
            longlong2 dv = *(const longlong2*)(ei + E + e0);
            s[0] = (int)sv.x; s[1] = (int)sv.y;
            d[0] = (int)dv.x; d[1] = (int)dv.y;
        } else {
            s[0] = (int)ei[e0];
            d[0] = (int)ei[E + e0];
        }
    } else {
        const int* ei = (const int*)ei_raw;
        if (n == 2) {
            int2 sv = *(const int2*)(ei + e0);
            int2 dv = *(const int2*)(ei + E + e0);
            s[0] = sv.x; s[1] = sv.y;
            d[0] = dv.x; d[1] = dv.y;
        } else {
            s[0] = ei[e0];
            d[0] = ei[E + e0];
        }
    }

    #pragma unroll
    for (int u = 0; u < 2; u++) {
        if (u >= n) break;
        int pos = atomicAdd(&g_cursor[d[u]], 1);
        if (pos < BUCKET_CAP) {
            g_bucket[(long long)d[u] * BUCKET_CAP + pos] = s[u];
        } else {
            int sp = atomicAdd(&g_spill_n, 1);
            if (sp < MAX_SPILL) { g_spill_src[sp] = s[u]; g_spill_dst[sp] = d[u]; }
        }
    }
}

// ---------------------------------------------------------------------------
// Kernel 3: aggregate. One warp per dest node; lane holds half2 (feats 2c,2c+1).
// Gathers 128B fp16 rows (L2-resident), accumulates fp32.
//   out[d] = feat[d] + (sum_src feat16[src] + deg*feat[d]) / max(deg,1)
// deg = true in-degree, so the deg*feat[d] term covers spilled edges too.
// ---------------------------------------------------------------------------
__global__ void aggregate_kernel(const float* __restrict__ feat,
                                 float* __restrict__ out,
                                 int n_nodes) {
    int warp = (blockIdx.x * blockDim.x + threadIdx.x) >> 5;
    int lane = threadIdx.x & 31;
    if (warp >= n_nodes) return;

    int v   = warp;
    int deg = g_cursor[v];
    int cnt = min(deg, BUCKET_CAP);
    const int* bucket = g_bucket + (long long)v * BUCKET_CAP;
    const __half2* h2 = (const __half2*)g_feat16;

    float2 acc = make_float2(0.0f, 0.0f);

    int k = 0;
    for (; k + 8 <= cnt; k += 8) {
        int sid[8];
        #pragma unroll
        for (int u = 0; u < 8; u++) sid[u] = bucket[k + u];
        #pragma unroll
        for (int u = 0; u < 8; u++) {
            float2 x = __half22float2(__ldg(&h2[(long long)sid[u] * 32 + lane]));
            acc.x += x.x;
            acc.y += x.y;
        }
    }
    for (; k < cnt; k++) {
        int s0 = bucket[k];
        float2 x = __half22float2(__ldg(&h2[(long long)s0 * 32 + lane]));
        acc.x += x.x;
        acc.y += x.y;
    }

    float2 fd = __ldg(&((const float2*)feat)[(long long)v * 32 + lane]);
    float fc  = (float)deg;
    float inv = 1.0f / (float)max(deg, 1);

    float2 r;
    r.x = fd.x + (acc.x + fc * fd.x) * inv;
    r.y = fd.y + (acc.y + fc * fd.y) * inv;
    ((float2*)out)[(long long)v * 32 + lane] = r;
}

// ---------------------------------------------------------------------------
// Kernel 4: spill fixup (normally 0 entries). Adds feat[src]*inv_deg (fp32
// exact) into out.
// ---------------------------------------------------------------------------
__global__ void spill_kernel(const float* __restrict__ feat,
                             float* __restrict__ out) {
    int n = g_spill_n;
    if (n > MAX_SPILL) n = MAX_SPILL;
    for (int idx = blockIdx.x * blockDim.x + threadIdx.x;
         idx < n * 64;
         idx += gridDim.x * blockDim.x) {
        int i = idx >> 6;
        int c = idx & 63;
        int s = g_spill_src[i];
        int d = g_spill_dst[i];
        float inv = 1.0f / (float)max(g_cursor[d], 1);
        atomicAdd(&out[(long long)d * 64 + c], feat[(long long)s * 64 + c] * inv);
    }
}

extern "C" void kernel_launch(void* const* d_in, const int* in_sizes, int n_in,
                              void* d_out, int out_size) {
    const float* feat = (const float*)d_in[0];
    const void* ei = d_in[1];
    float* out = (float*)d_out;

    int n_nodes = in_sizes[0] / 64;            // 100000
    long long E = (long long)in_sizes[1] / 2;  // 1600000

    {
        int total = n_nodes * 32;              // half2 elements
        convert_kernel<<<(total + 255) / 256, 256>>>(feat, (const int*)ei, 2 * E, n_nodes);
    }

    {
        long long nthreads = (E + 1) / 2;      // 2 edges per thread
        int threads = 256;
        long long blocks = (nthreads + threads - 1) / threads;
        fill_kernel<<<(unsigned int)blocks, threads>>>(ei, E);
    }

    {
        long long total = (long long)n_nodes * 32;   // one warp per node
        int threads = 256;
        long long blocks = (total + threads - 1) / threads;
        aggregate_kernel<<<(unsigned int)blocks, threads>>>(feat, out, n_nodes);
    }

    spill_kernel<<<16, 256>>>(feat, out);
}

// round 11
// speedup vs baseline: 1.0715x; 1.0715x over previous
#include <cuda_runtime.h>
#include <stdint.h>

// Static scratch (no device allocs allowed).
#define MAX_NODES 131072
#define BUCKET_CAP 64
#define MAX_SPILL 8192

__device__ int g_cursor[MAX_NODES];                 // per-node fill cursor == in-degree
__device__ int g_bucket[MAX_NODES * BUCKET_CAP];    // src ids, 64 slots per node
__device__ int g_spill_src[MAX_SPILL];
__device__ int g_spill_dst[MAX_SPILL];
__device__ int g_spill_n;
__device__ int g_is64;                              // edge index dtype flag

// ---------------------------------------------------------------------------
// Kernel 1: zero cursors + spill counter; block 0 sniffs edge-index dtype
// (int64 values < 2^31 have zero odd int32 words; int32 node ids are
// ~uniform in [0,1e5) and essentially never all zero over 2048 samples).
// ---------------------------------------------------------------------------
__global__ void init_kernel(const int* __restrict__ ei32, long long n_words,
                            int n_nodes) {
    int i = blockIdx.x * blockDim.x + threadIdx.x;
    if (i < n_nodes) g_cursor[i] = 0;
    if (i == 0) g_spill_n = 0;

    if (blockIdx.x == 0) {
        __shared__ int nz;
        if (threadIdx.x == 0) nz = 0;
        __syncthreads();
        long long limit = n_words < 4096 ? n_words : 4096;
        for (long long j = threadIdx.x * 2 + 1; j < limit; j += blockDim.x * 2)
            if (ei32[j] != 0) atomicOr(&nz, 1);
        __syncthreads();
        if (threadIdx.x == 0) g_is64 = (nz == 0) ? 1 : 0;
    }
}

// ---------------------------------------------------------------------------
// Kernel 2: single edge pass — scatter src ids into fixed-capacity buckets.
// Two edges per thread, vectorized index loads. Overflow (P ~ 1e-18/node)
// goes to the spill list.
// ---------------------------------------------------------------------------
__global__ void fill_kernel(const void* __restrict__ ei_raw, long long E) {
    long long t = (long long)blockIdx.x * blockDim.x + threadIdx.x;
    long long e0 = t * 2;
    if (e0 >= E) return;

    int s[2], d[2];
    int n = (e0 + 1 < E) ? 2 : 1;

    if (g_is64) {
        const long long* ei = (const long long*)ei_raw;
        if (n == 2) {
            longlong2 sv = *(const longlong2*)(ei + e0);
            longlong2 dv = *(const longlong2*)(ei + E + e0);
            s[0] = (int)sv.x; s[1] = (int)sv.y;
            d[0] = (int)dv.x; d[1] = (int)dv.y;
        } else {
            s[0] = (int)ei[e0];
            d[0] = (int)ei[E + e0];
        }
    } else {
        const int* ei = (const int*)ei_raw;
        if (n == 2) {
            int2 sv = *(const int2*)(ei + e0);
            int2 dv = *(const int2*)(ei + E + e0);
            s[0] = sv.x; s[1] = sv.y;
            d[0] = dv.x; d[1] = dv.y;
        } else {
            s[0] = ei[e0];
            d[0] = ei[E + e0];
        }
    }

    #pragma unroll
    for (int u = 0; u < 2; u++) {
        if (u >= n) break;
        int pos = atomicAdd(&g_cursor[d[u]], 1);
        if (pos < BUCKET_CAP) {
            g_bucket[(long long)d[u] * BUCKET_CAP + pos] = s[u];
        } else {
            int sp = atomicAdd(&g_spill_n, 1);
            if (sp < MAX_SPILL) { g_spill_src[sp] = s[u]; g_spill_dst[sp] = d[u]; }
        }
    }
}

// ---------------------------------------------------------------------------
// Kernel 3: aggregate (+ fused spill fixup). One warp per dest node, float2
// per lane (64 feats). Indices loaded coalesced once per warp and distributed
// via shuffles; gathers are 256B fp32 rows (L2-resident), unrolled x8 for MLP.
//   out[d] = feat[d] + (sum_src feat[src] + deg*feat[d]) / max(deg,1)
// deg = true in-degree, so the deg*feat[d] term covers spilled edges; the
// cold-path scan below adds their missing feat[src] parts.
// ---------------------------------------------------------------------------
__global__ void aggregate_kernel(const float* __restrict__ feat,
                                 float* __restrict__ out,
                                 int n_nodes) {
    int warp = (blockIdx.x * blockDim.x + threadIdx.x) >> 5;
    int lane = threadIdx.x & 31;
    if (warp >= n_nodes) return;

    int v   = warp;
    int deg = g_cursor[v];
    int cnt = min(deg, BUCKET_CAP);
    const int* bucket = g_bucket + (long long)v * BUCKET_CAP;
    const float2* f2 = (const float2*)feat;

    // Coalesced index prefetch: 2 LDGs cover all <=64 indices.
    int idx0 = (lane < cnt)      ? bucket[lane]      : 0;
    int idx1 = (32 + lane < cnt) ? bucket[32 + lane] : 0;

    float2 acc = make_float2(0.0f, 0.0f);

    int k = 0;
    for (; k + 8 <= cnt; k += 8) {
        int sid[8];
        #pragma unroll
        for (int u = 0; u < 8; u++) {
            int kk = k + u;
            sid[u] = __shfl_sync(0xFFFFFFFFu, (kk < 32) ? idx0 : idx1, kk & 31);
        }
        #pragma unroll
        for (int u = 0; u < 8; u++) {
            float2 x = __ldg(&f2[(long long)sid[u] * 32 + lane]);
            acc.x += x.x;
            acc.y += x.y;
        }
    }
    for (; k < cnt; k++) {
        int sid = __shfl_sync(0xFFFFFFFFu, (k < 32) ? idx0 : idx1, k & 31);
        float2 x = __ldg(&f2[(long long)sid * 32 + lane]);
        acc.x += x.x;
        acc.y += x.y;
    }

    // Fused spill fixup: normally g_spill_n == 0 -> one broadcast load.
    int spn = g_spill_n;
    if (spn > 0) {
        if (spn > MAX_SPILL) spn = MAX_SPILL;
        for (int i = 0; i < spn; i++) {
            if (g_spill_dst[i] == v) {
                float2 x = __ldg(&f2[(long long)g_spill_src[i] * 32 + lane]);
                acc.x += x.x;
                acc.y += x.y;
            }
        }
    }

    float2 fd = __ldg(&f2[(long long)v * 32 + lane]);
    float fc  = (float)deg;
    float inv = 1.0f / (float)max(deg, 1);

    float2 r;
    r.x = fd.x + (acc.x + fc * fd.x) * inv;
    r.y = fd.y + (acc.y + fc * fd.y) * inv;
    ((float2*)out)[(long long)v * 32 + lane] = r;
}

extern "C" void kernel_launch(void* const* d_in, const int* in_sizes, int n_in,
                              void* d_out, int out_size) {
    const float* feat = (const float*)d_in[0];
    const void* ei = d_in[1];
    float* out = (float*)d_out;

    int n_nodes = in_sizes[0] / 64;            // 100000
    long long E = (long long)in_sizes[1] / 2;  // 1600000

    init_kernel<<<(n_nodes + 255) / 256, 256>>>((const int*)ei, 2 * E, n_nodes);

    {
        long long nthreads = (E + 1) / 2;      // 2 edges per thread
        int threads = 256;
        long long blocks = (nthreads + threads - 1) / threads;
        fill_kernel<<<(unsigned int)blocks, threads>>>(ei, E);
    }

    {
        long long total = (long long)n_nodes * 32;   // one warp per node
        int threads = 256;
        long long blocks = (total + threads - 1) / threads;
        aggregate_kernel<<<(unsigned int)blocks, threads>>>(feat, out, n_nodes);
    }
}

// round 12
// speedup vs baseline: 1.0952x; 1.0221x over previous
#include <cuda_runtime.h>
#include <stdint.h>

// Static scratch (no device allocs allowed).
#define MAX_NODES 131072
#define BUCKET_CAP 64
#define MAX_SPILL 8192

__device__ int g_cursor[MAX_NODES];                 // per-node fill cursor == in-degree
__device__ int g_bucket[MAX_NODES * BUCKET_CAP];    // src ids, 64 slots per node
__device__ int g_spill_src[MAX_SPILL];
__device__ int g_spill_dst[MAX_SPILL];
__device__ int g_spill_n;
__device__ int g_is64;                              // edge index dtype flag

// ---------------------------------------------------------------------------
// Kernel 1: zero cursors + spill counter; block 0 sniffs edge-index dtype.
// int64 values < 2^31 have zero odd int32 words; int32 node ids are ~uniform
// in [0,1e5): P(128 odd words all zero | int32) ~ 1e-640. One coalesced 1KB
// read instead of a strided 16KB scan.
// ---------------------------------------------------------------------------
__global__ void init_kernel(const int* __restrict__ ei32, long long n_words,
                            int n_nodes) {
    int i = blockIdx.x * blockDim.x + threadIdx.x;
    if (i < n_nodes) g_cursor[i] = 0;
    if (i == 0) g_spill_n = 0;

    if (blockIdx.x == 0) {
        __shared__ int nz;
        if (threadIdx.x == 0) nz = 0;
        __syncthreads();
        long long limit = n_words < 256 ? n_words : 256;
        long long j = threadIdx.x;            // one word per thread
        if (j < limit && (j & 1) && ei32[j] != 0) atomicOr(&nz, 1);
        __syncthreads();
        if (threadIdx.x == 0) g_is64 = (nz == 0) ? 1 : 0;
    }
}

// ---------------------------------------------------------------------------
// Kernel 2: single edge pass — scatter src ids into fixed-capacity buckets.
// Overflow (vanishingly rare, P~1e-18/node) goes to the spill list.
// ---------------------------------------------------------------------------
__global__ void fill_kernel(const void* __restrict__ ei_raw, long long E) {
    long long e = (long long)blockIdx.x * blockDim.x + threadIdx.x;
    if (e >= E) return;
    int s, d;
    if (g_is64) {
        const long long* ei = (const long long*)ei_raw;
        s = (int)ei[e];
        d = (int)ei[E + e];
    } else {
        const int* ei = (const int*)ei_raw;
        s = ei[e];
        d = ei[E + e];
    }
    int pos = atomicAdd(&g_cursor[d], 1);
    if (pos < BUCKET_CAP) {
        g_bucket[(long long)d * BUCKET_CAP + pos] = s;
    } else {
        int sp = atomicAdd(&g_spill_n, 1);
        if (sp < MAX_SPILL) { g_spill_src[sp] = s; g_spill_dst[sp] = d; }
    }
}

// ---------------------------------------------------------------------------
// Kernel 3: aggregate (+ fused spill fixup). One warp per dest node, float2
// per lane (64 feats). Index loads are warp-broadcast (1 L1 wavefront each,
// bucket row L1-resident); gathers are 256B fp32 rows (L2-resident), x8 MLP.
//   out[d] = feat[d] + (sum_src feat[src] + deg*feat[d]) / max(deg,1)
// deg = true in-degree, so the deg*feat[d] term covers spilled edges; the
// cold-path scan adds their missing feat[src] parts.
// ---------------------------------------------------------------------------
__global__ void aggregate_kernel(const float* __restrict__ feat,
                                 float* __restrict__ out,
                                 int n_nodes) {
    int warp = (blockIdx.x * blockDim.x + threadIdx.x) >> 5;
    int lane = threadIdx.x & 31;
    if (warp >= n_nodes) return;

    int v   = warp;
    int deg = g_cursor[v];
    int cnt = min(deg, BUCKET_CAP);
    const int* bucket = g_bucket + (long long)v * BUCKET_CAP;
    const float2* f2 = (const float2*)feat;

    float2 acc = make_float2(0.0f, 0.0f);

    int k = 0;
    for (; k + 8 <= cnt; k += 8) {
        int sid[8];
        #pragma unroll
        for (int u = 0; u < 8; u++) sid[u] = bucket[k + u];
        #pragma unroll
        for (int u = 0; u < 8; u++) {
            float2 x = __ldg(&f2[(long long)sid[u] * 32 + lane]);
            acc.x += x.x;
            acc.y += x.y;
        }
    }
    for (; k < cnt; k++) {
        int s0 = bucket[k];
        float2 x0 = __ldg(&f2[(long long)s0 * 32 + lane]);
        acc.x += x0.x;
        acc.y += x0.y;
    }

    // Fused spill fixup: normally g_spill_n == 0 -> one broadcast load.
    int spn = g_spill_n;
    if (spn > 0) {
        if (spn > MAX_SPILL) spn = MAX_SPILL;
        for (int i = 0; i < spn; i++) {
            if (g_spill_dst[i] == v) {
                float2 x = __ldg(&f2[(long long)g_spill_src[i] * 32 + lane]);
                acc.x += x.x;
                acc.y += x.y;
            }
        }
    }

    float2 fd = __ldg(&f2[(long long)v * 32 + lane]);
    float fc  = (float)deg;
    float inv = 1.0f / (float)max(deg, 1);

    float2 r;
    r.x = fd.x + (acc.x + fc * fd.x) * inv;
    r.y = fd.y + (acc.y + fc * fd.y) * inv;
    ((float2*)out)[(long long)v * 32 + lane] = r;
}

extern "C" void kernel_launch(void* const* d_in, const int* in_sizes, int n_in,
                              void* d_out, int out_size) {
    const float* feat = (const float*)d_in[0];
    const void* ei = d_in[1];
    float* out = (float*)d_out;

    int n_nodes = in_sizes[0] / 64;            // 100000
    long long E = (long long)in_sizes[1] / 2;  // 1600000

    init_kernel<<<(n_nodes + 255) / 256, 256>>>((const int*)ei, 2 * E, n_nodes);

    {
        int threads = 256;
        long long blocks = (E + threads - 1) / threads;
        fill_kernel<<<(unsigned int)blocks, threads>>>(ei, E);
    }

    {
        long long total = (long long)n_nodes * 32;   // one warp per node
        int threads = 256;
        long long blocks = (total + threads - 1) / threads;
        aggregate_kernel<<<(unsigned int)blocks, threads>>>(feat, out, n_nodes);
    }
}

// round 15
// speedup vs baseline: 1.1730x; 1.0711x over previous
#include <cuda_runtime.h>
#include <stdint.h>

// Static scratch (no device allocs allowed).
#define MAX_NODES 131072
#define BUCKET_CAP 64
#define MAX_SPILL 8192

__device__ int g_cursor[MAX_NODES];                 // per-node fill cursor == in-degree
__device__ int g_bucket[MAX_NODES * BUCKET_CAP];    // src ids, 64 slots per node
__device__ int g_spill_src[MAX_SPILL];
__device__ int g_spill_dst[MAX_SPILL];
__device__ int g_spill_n;
__device__ int g_is64;                              // edge index dtype flag

// ---------------------------------------------------------------------------
// Kernel 1: zero cursors + spill counter; block 0 sniffs edge-index dtype.
// int64 values < 2^31 have zero odd int32 words; int32 node ids are ~uniform
// in [0,1e5): P(128 odd words all zero | int32) ~ 1e-640.
// ---------------------------------------------------------------------------
__global__ void init_kernel(const int* __restrict__ ei32, long long n_words,
                            int n_nodes) {
    int i = blockIdx.x * blockDim.x + threadIdx.x;
    if (i < n_nodes) g_cursor[i] = 0;
    if (i == 0) g_spill_n = 0;

    if (blockIdx.x == 0) {
        __shared__ int nz;
        if (threadIdx.x == 0) nz = 0;
        __syncthreads();
        long long limit = n_words < 256 ? n_words : 256;
        long long j = threadIdx.x;            // one word per thread
        if (j < limit && (j & 1) && ei32[j] != 0) atomicOr(&nz, 1);
        __syncthreads();
        if (threadIdx.x == 0) g_is64 = (nz == 0) ? 1 : 0;
    }
}

// ---------------------------------------------------------------------------
// Kernel 2: single edge pass — scatter src ids into fixed-capacity buckets.
// Overflow (vanishingly rare, P~1e-18/node) goes to the spill list.
// ---------------------------------------------------------------------------
__global__ void fill_kernel(const void* __restrict__ ei_raw, long long E) {
    long long e = (long long)blockIdx.x * blockDim.x + threadIdx.x;
    if (e >= E) return;
    int s, d;
    if (g_is64) {
        const long long* ei = (const long long*)ei_raw;
        s = (int)ei[e];
        d = (int)ei[E + e];
    } else {
        const int* ei = (const int*)ei_raw;
        s = ei[e];
        d = ei[E + e];
    }
    int pos = atomicAdd(&g_cursor[d], 1);
    if (pos < BUCKET_CAP) {
        g_bucket[(long long)d * BUCKET_CAP + pos] = s;
    } else {
        int sp = atomicAdd(&g_spill_n, 1);
        if (sp < MAX_SPILL) { g_spill_src[sp] = s; g_spill_dst[sp] = d; }
    }
}

// ---------------------------------------------------------------------------
// Kernel 3: aggregate (+ fused spill fixup). One warp per dest node.
// Half-warp float4 layout: lanes 0-15 and 16-31 each gather a FULL 256B
// feature row (16 x float4) for two different srcs in parallel. Per 8 srcs:
// 2 broadcast int4 index loads + 4 LDG.128 gathers (vs 16 LDGs in the
// scalar scheme). Halves merged once per node via shfl_xor.
//   out[d] = feat[d] + (sum_src feat[src] + deg*feat[d]) / max(deg,1)
// ---------------------------------------------------------------------------
__global__ void aggregate_kernel(const float* __restrict__ feat,
                                 float* __restrict__ out,
                                 int n_nodes) {
    int warp = (blockIdx.x * blockDim.x + threadIdx.x) >> 5;
    int lane = threadIdx.x & 31;
    if (warp >= n_nodes) return;

    int half  = lane >> 4;      // 0 or 1: which src of the pair
    int qlane = lane & 15;      // feature chunk (float4) index

    int v   = warp;
    int deg = g_cursor[v];
    int cnt = min(deg, BUCKET_CAP);
    const int* bucket = g_bucket + (long long)v * BUCKET_CAP;
    const float4* f4 = (const float4*)feat;

    float4 acc = make_float4(0.0f, 0.0f, 0.0f, 0.0f);

    int k = 0;
    // 8 srcs per iter: 2 broadcast int4 idx loads + 4 gather LDG.128s.
    for (; k + 8 <= cnt; k += 8) {
        int4 ia = *(const int4*)(bucket + k);
        int4 ib = *(const int4*)(bucket + k + 4);
        int s0 = half ? ia.y : ia.x;
        int s1 = half ? ia.w : ia.z;
        int s2 = half ? ib.y : ib.x;
        int s3 = half ? ib.w : ib.z;
        float4 x0 = __ldg(&f4[(long long)s0 * 16 + qlane]);
        float4 x1 = __ldg(&f4[(long long)s1 * 16 + qlane]);
        float4 x2 = __ldg(&f4[(long long)s2 * 16 + qlane]);
        float4 x3 = __ldg(&f4[(long long)s3 * 16 + qlane]);
        acc.x += x0.x + x1.x + x2.x + x3.x;
        acc.y += x0.y + x1.y + x2.y + x3.y;
        acc.z += x0.z + x1.z + x2.z + x3.z;
        acc.w += x0.w + x1.w + x2.w + x3.w;
    }
    // pair tail
    for (; k + 2 <= cnt; k += 2) {
        int2 id = *(const int2*)(bucket + k);
        int s = half ? id.y : id.x;
        float4 x = __ldg(&f4[(long long)s * 16 + qlane]);
        acc.x += x.x; acc.y += x.y; acc.z += x.z; acc.w += x.w;
    }
    // single tail: only half 0 adds it
    if (k < cnt && half == 0) {
        int s = bucket[k];
        float4 x = __ldg(&f4[(long long)s * 16 + qlane]);
        acc.x += x.x; acc.y += x.y; acc.z += x.z; acc.w += x.w;
    }

    // Fused spill fixup (normally g_spill_n == 0): add on half 0 only.
    int spn = g_spill_n;
    if (spn > 0) {
        if (spn > MAX_SPILL) spn = MAX_SPILL;
        for (int i = 0; i < spn; i++) {
            if (g_spill_dst[i] == v && half == 0) {
                float4 x = __ldg(&f4[(long long)g_spill_src[i] * 16 + qlane]);
                acc.x += x.x; acc.y += x.y; acc.z += x.z; acc.w += x.w;
            }
        }
    }

    // Merge the two half-warp partial sums.
    acc.x += __shfl_xor_sync(0xFFFFFFFFu, acc.x, 16);
    acc.y += __shfl_xor_sync(0xFFFFFFFFu, acc.y, 16);
    acc.z += __shfl_xor_sync(0xFFFFFFFFu, acc.z, 16);
    acc.w += __shfl_xor_sync(0xFFFFFFFFu, acc.w, 16);

    if (half == 0) {
        float4 fd = __ldg(&f4[(long long)v * 16 + qlane]);
        float fc  = (float)deg;
        float inv = 1.0f / (float)max(deg, 1);
        float4 r;
        r.x = fd.x + (acc.x + fc * fd.x) * inv;
        r.y = fd.y + (acc.y + fc * fd.y) * inv;
        r.z = fd.z + (acc.z + fc * fd.z) * inv;
        r.w = fd.w + (acc.w + fc * fd.w) * inv;
        ((float4*)out)[(long long)v * 16 + qlane] = r;
    }
}

extern "C" void kernel_launch(void* const* d_in, const int* in_sizes, int n_in,
                              void* d_out, int out_size) {
    const float* feat = (const float*)d_in[0];
    const void* ei = d_in[1];
    float* out = (float*)d_out;

    int n_nodes = in_sizes[0] / 64;            // 100000
    long long E = (long long)in_sizes[1] / 2;  // 1600000

    init_kernel<<<(n_nodes + 255) / 256, 256>>>((const int*)ei, 2 * E, n_nodes);

    {
        int threads = 256;
        long long blocks = (E + threads - 1) / threads;
        fill_kernel<<<(unsigned int)blocks, threads>>>(ei, E);
    }

    {
        long long total = (long long)n_nodes * 32;   // one warp per node
        int threads = 256;
        long long blocks = (total + threads - 1) / threads;
        aggregate_kernel<<<(unsigned int)blocks, threads>>>(feat, out, n_nodes);
    }
}